// round 2
// baseline (speedup 1.0000x reference)
#include <cuda_runtime.h>
#include <math.h>

#define PI_F 3.14159f

// Fixed problem shape (from setup_inputs): B=4, C=D=256, H=W=64, P=256
#define Bsz 4
#define Dd  256
#define Hh  64
#define Ww  64
#define Pp  256

// Per-(b,d) transform parameters, produced by params_kernel, consumed by sample_kernel.
__device__ float g_scale[Bsz * Dd];
__device__ float g_cos[Bsz * Dd];
__device__ float g_sin[Bsz * Dd];
__device__ float g_t0[Bsz * Dd];
__device__ float g_t1[Bsz * Dd];

__global__ void params_kernel(const float* __restrict__ para,
                              const float* __restrict__ W_c, const float* __restrict__ b_c,
                              const float* __restrict__ W_s, const float* __restrict__ b_s,
                              const float* __restrict__ W_r, const float* __restrict__ b_r,
                              const float* __restrict__ W_t, const float* __restrict__ b_t) {
    __shared__ float spara[Pp];
    __shared__ float sp[Pp];
    const int b = blockIdx.x;
    const int t = threadIdx.x;

    spara[t] = para[b * Pp + t];
    __syncthreads();

    // p = relu(para @ W_c + b_c)   (W_c is [P, P] row-major; thread t owns column t)
    float acc = 0.0f;
#pragma unroll 8
    for (int k = 0; k < Pp; ++k)
        acc = fmaf(spara[k], W_c[k * Pp + t], acc);
    acc += b_c[t];
    sp[t] = fmaxf(acc, 0.0f);
    __syncthreads();

    // scale / angle / translation heads
    float as = 0.0f, ar = 0.0f, at0 = 0.0f, at1 = 0.0f;
#pragma unroll 4
    for (int k = 0; k < Pp; ++k) {
        float pk = sp[k];
        as  = fmaf(pk, W_s[k * Pp + t], as);
        ar  = fmaf(pk, W_r[k * Pp + t], ar);
        at0 = fmaf(pk, W_t[k * (2 * Pp) + 2 * t],     at0);
        at1 = fmaf(pk, W_t[k * (2 * Pp) + 2 * t + 1], at1);
    }
    as  += b_s[t];
    ar  += b_r[t];
    at0 += b_t[2 * t];
    at1 += b_t[2 * t + 1];

    float scale = 2.0f / (1.0f + expf(-as));       // sigmoid * 2
    float angle = tanhf(ar) * PI_F;

    const int idx = b * Dd + t;
    g_scale[idx] = scale;
    g_cos[idx]   = cosf(angle);
    g_sin[idx]   = sinf(angle);
    g_t0[idx]    = tanhf(at0);
    g_t1[idx]    = tanhf(at1);
}

__device__ __forceinline__ float plane_fetch(const float* pl, int y, int x) {
    return (x >= 0 && x < Ww && y >= 0 && y < Hh) ? pl[y * Ww + x] : 0.0f;
}

__global__ void __launch_bounds__(256) sample_kernel(const float* __restrict__ vol,
                                                     float* __restrict__ out) {
    __shared__ float plane0[Hh * Ww];
    __shared__ float plane1[Hh * Ww];

    const int bd = blockIdx.x;           // 0 .. B*D-1
    const int b = bd >> 8;
    const int d = bd & 255;

    const float sc = g_scale[bd];
    const float c  = g_cos[bd];
    const float s  = g_sin[bd];
    const float t0 = g_t0[bd];
    const float t1 = g_t1[bd];

    // z coordinate -> iz (replicates reference op order)
    const float gz = 2.0f * ((float)d / (float)(Dd - 1)) - 1.0f;
    const float iz = ((gz + 1.0f) * (float)Dd - 1.0f) * 0.5f;
    const float z0f = floorf(iz);
    const float wz = iz - z0f;
    const int z0 = (int)z0f;

    const float* base = vol + (size_t)b * Dd * Hh * Ww;
    const bool z0ok = (z0 >= 0) && (z0 < Dd);
    const bool z1ok = (z0 + 1 >= 0) && (z0 + 1 < Dd);
    const float* p0src = base + (size_t)(z0ok ? z0 : 0) * (Hh * Ww);
    const float* p1src = base + (size_t)(z1ok ? z0 + 1 : 0) * (Hh * Ww);

    // coalesced plane loads (zero-fill if z out of range -> zero padding semantics)
    for (int i = threadIdx.x; i < Hh * Ww; i += blockDim.x) {
        plane0[i] = z0ok ? p0src[i] : 0.0f;
        plane1[i] = z1ok ? p1src[i] : 0.0f;
    }
    __syncthreads();

    const float wz1 = wz;
    const float wz0 = 1.0f - wz;
    float* outp = out + (size_t)bd * (Hh * Ww);

    for (int i = threadIdx.x; i < Hh * Ww; i += blockDim.x) {
        const int px = i & (Ww - 1);
        const int py = i >> 6;

        const float gx = 2.0f * ((float)px / (float)(Ww - 1)) - 1.0f;
        const float gy = 2.0f * ((float)py / (float)(Hh - 1)) - 1.0f;

        const float tx = (c * gx - s * gy) * sc + t0;
        const float ty = (s * gx + c * gy) * sc + t1;

        const float ix = ((tx + 1.0f) * (float)Ww - 1.0f) * 0.5f;
        const float iy = ((ty + 1.0f) * (float)Hh - 1.0f) * 0.5f;

        const float x0f = floorf(ix);
        const float y0f = floorf(iy);
        const float wx = ix - x0f;
        const float wy = iy - y0f;
        const int x0 = (int)x0f;
        const int y0 = (int)y0f;

        const float a00 = plane_fetch(plane0, y0,     x0);
        const float a01 = plane_fetch(plane0, y0,     x0 + 1);
        const float a10 = plane_fetch(plane0, y0 + 1, x0);
        const float a11 = plane_fetch(plane0, y0 + 1, x0 + 1);

        const float c00 = plane_fetch(plane1, y0,     x0);
        const float c01 = plane_fetch(plane1, y0,     x0 + 1);
        const float c10 = plane_fetch(plane1, y0 + 1, x0);
        const float c11 = plane_fetch(plane1, y0 + 1, x0 + 1);

        const float wx1 = wx, wx0 = 1.0f - wx;
        const float wy1 = wy, wy0 = 1.0f - wy;

        const float v0 = (a00 * wx0 + a01 * wx1) * wy0 + (a10 * wx0 + a11 * wx1) * wy1;
        const float v1 = (c00 * wx0 + c01 * wx1) * wy0 + (c10 * wx0 + c11 * wx1) * wy1;

        outp[i] = v0 * wz0 + v1 * wz1;
    }
}

extern "C" void kernel_launch(void* const* d_in, const int* in_sizes, int n_in,
                              void* d_out, int out_size) {
    const float* feature_map = (const float*)d_in[0];
    const float* para_code   = (const float*)d_in[1];
    const float* W_c = (const float*)d_in[2];
    const float* b_c = (const float*)d_in[3];
    const float* W_s = (const float*)d_in[4];
    const float* b_s = (const float*)d_in[5];
    const float* W_r = (const float*)d_in[6];
    const float* b_r = (const float*)d_in[7];
    const float* W_t = (const float*)d_in[8];
    const float* b_t = (const float*)d_in[9];
    float* out = (float*)d_out;

    params_kernel<<<Bsz, Pp>>>(para_code, W_c, b_c, W_s, b_s, W_r, b_r, W_t, b_t);
    sample_kernel<<<Bsz * Dd, 256>>>(feature_map, out);
}

// round 3
// speedup vs baseline: 2.1427x; 2.1427x over previous
#include <cuda_runtime.h>
#include <math.h>

#define PI_F 3.14159f

// Fixed problem shape: B=4, D=C=256, H=W=64, P=256
#define Bsz 4
#define Dd  256
#define Hh  64
#define Ww  64
#define Pp  256

// Per-(b,d) transform parameters
__device__ float g_scale[Bsz * Dd];
__device__ float g_cos[Bsz * Dd];
__device__ float g_sin[Bsz * Dd];
__device__ float g_t0[Bsz * Dd];
__device__ float g_t1[Bsz * Dd];

// ---------------------------------------------------------------------------
// params kernel: 1024 threads/block, k-dimension split 4 ways for MLP + issue
// ---------------------------------------------------------------------------
__global__ void __launch_bounds__(1024) params_kernel(
        const float* __restrict__ para,
        const float* __restrict__ W_c, const float* __restrict__ b_c,
        const float* __restrict__ W_s, const float* __restrict__ b_s,
        const float* __restrict__ W_r, const float* __restrict__ b_r,
        const float* __restrict__ W_t, const float* __restrict__ b_t) {
    __shared__ float spara[Pp];
    __shared__ float sp[Pp];
    __shared__ float part1[4][Pp];
    __shared__ float part2[4][Pp][4];   // 16 KB

    const int b   = blockIdx.x;
    const int tid = threadIdx.x;
    const int t   = tid & 255;
    const int j   = tid >> 8;           // k-split index 0..3

    if (j == 0) spara[t] = para[b * Pp + t];
    __syncthreads();

    // stage 1: p = relu(para @ W_c + b_c), k-split 4 ways
    {
        float acc = 0.0f;
        const int k0 = j * 64;
#pragma unroll 8
        for (int kk = 0; kk < 64; ++kk) {
            const int k = k0 + kk;
            acc = fmaf(spara[k], W_c[k * Pp + t], acc);
        }
        part1[j][t] = acc;
    }
    __syncthreads();
    if (j == 0) {
        float v = part1[0][t] + part1[1][t] + part1[2][t] + part1[3][t] + b_c[t];
        sp[t] = fmaxf(v, 0.0f);
    }
    __syncthreads();

    // stage 2: four heads, k-split 4 ways
    {
        float as = 0.0f, ar = 0.0f, at0 = 0.0f, at1 = 0.0f;
        const int k0 = j * 64;
        const float2* __restrict__ W_t2 = (const float2*)W_t;
#pragma unroll 4
        for (int kk = 0; kk < 64; ++kk) {
            const int k = k0 + kk;
            const float pk = sp[k];
            as  = fmaf(pk, W_s[k * Pp + t], as);
            ar  = fmaf(pk, W_r[k * Pp + t], ar);
            const float2 wt = W_t2[k * Pp + t];
            at0 = fmaf(pk, wt.x, at0);
            at1 = fmaf(pk, wt.y, at1);
        }
        part2[j][t][0] = as;
        part2[j][t][1] = ar;
        part2[j][t][2] = at0;
        part2[j][t][3] = at1;
    }
    __syncthreads();

    if (j == 0) {
        float as  = part2[0][t][0] + part2[1][t][0] + part2[2][t][0] + part2[3][t][0] + b_s[t];
        float ar  = part2[0][t][1] + part2[1][t][1] + part2[2][t][1] + part2[3][t][1] + b_r[t];
        float at0 = part2[0][t][2] + part2[1][t][2] + part2[2][t][2] + part2[3][t][2] + b_t[2 * t];
        float at1 = part2[0][t][3] + part2[1][t][3] + part2[2][t][3] + part2[3][t][3] + b_t[2 * t + 1];

        const float scale = 2.0f / (1.0f + expf(-as));
        const float angle = tanhf(ar) * PI_F;

        const int idx = b * Dd + t;
        g_scale[idx] = scale;
        g_cos[idx]   = cosf(angle);
        g_sin[idx]   = sinf(angle);
        g_t0[idx]    = tanhf(at0);
        g_t1[idx]    = tanhf(at1);
    }
}

// ---------------------------------------------------------------------------
// sample kernel: one CTA per (b,d). Planes interleaved as float2 with a
// 2-wide zero halo; clamp-to-halo reproduces zero padding with no branches.
// ---------------------------------------------------------------------------
#define PAD   2
#define PITCH (Ww + 2 * PAD)            // 68
#define PROWS (Hh + 2 * PAD)            // 68

__global__ void __launch_bounds__(512) sample_kernel(const float* __restrict__ vol,
                                                     float* __restrict__ out) {
    __shared__ float2 sh[PROWS * PITCH];   // ~37 KB

    const int bd  = blockIdx.x;
    const int b   = bd >> 8;
    const int d   = bd & 255;
    const int tid = threadIdx.x;

    const float sc = g_scale[bd];
    const float c  = g_cos[bd];
    const float s  = g_sin[bd];
    const float t0 = g_t0[bd];
    const float t1 = g_t1[bd];

    // z -> iz (reference op order)
    const float gz  = 2.0f * ((float)d / (float)(Dd - 1)) - 1.0f;
    const float iz  = ((gz + 1.0f) * (float)Dd - 1.0f) * 0.5f;
    const float z0f = floorf(iz);
    const float wz1 = iz - z0f;
    const float wz0 = 1.0f - wz1;
    const int   z0  = (int)z0f;

    const float* base  = vol + (size_t)b * Dd * Hh * Ww;
    const bool z0ok = (z0 >= 0) && (z0 < Dd);
    const bool z1ok = (z0 + 1 >= 0) && (z0 + 1 < Dd);
    const float4* p0v = (const float4*)(base + (size_t)(z0ok ? z0 : 0) * (Hh * Ww));
    const float4* p1v = (const float4*)(base + (size_t)(z1ok ? z0 + 1 : 0) * (Hh * Ww));

    // zero whole padded buffer (halo), vectorized
    {
        float4* shz = (float4*)sh;
        const int n4 = (PROWS * PITCH) / 2;          // 2312 float4
#pragma unroll
        for (int i = tid; i < n4; i += 512)
            shz[i] = make_float4(0.f, 0.f, 0.f, 0.f);
    }
    __syncthreads();

    // interleaved fill of the interior: sh[y][x] = (plane0, plane1)
    const float4 zero4 = make_float4(0.f, 0.f, 0.f, 0.f);
#pragma unroll
    for (int jj = 0; jj < 2; ++jj) {
        const int g  = tid + jj * 512;               // 1024 groups of 4 floats
        const int y  = g >> 4;
        const int x4 = (g & 15) << 2;
        const float4 a = z0ok ? p0v[g] : zero4;
        const float4 bb = z1ok ? p1v[g] : zero4;
        float4* dst = (float4*)&sh[(y + PAD) * PITCH + (x4 + PAD)];
        dst[0] = make_float4(a.x, bb.x, a.y, bb.y);
        dst[1] = make_float4(a.z, bb.z, a.w, bb.w);
    }
    __syncthreads();

    // px constant per thread; py = py0 + 8k  ->  ix, iy affine in k
    const int px  = tid & 63;
    const int py0 = tid >> 6;                        // 0..7

    const float gx  = fmaf((float)px,  2.0f / 63.0f, -1.0f);
    const float gy0 = fmaf((float)py0, 2.0f / 63.0f, -1.0f);
    const float dgy = 8.0f * (2.0f / 63.0f);

    const float tx0 = (c * gx - s * gy0) * sc + t0;
    const float ty0 = (s * gx + c * gy0) * sc + t1;
    // ix = ((tx+1)*64-1)*0.5 = tx*32 + 31.5
    const float ix0 = fmaf(tx0, 32.0f, 31.5f);
    const float iy0 = fmaf(ty0, 32.0f, 31.5f);
    const float dix = -s * sc * dgy * 32.0f;
    const float diy =  c * sc * dgy * 32.0f;

    float* outp = out + (size_t)bd * (Hh * Ww) + py0 * Ww + px;

#pragma unroll
    for (int k = 0; k < 8; ++k) {
        const float kf = (float)k;
        const float ix = fmaf(kf, dix, ix0);
        const float iy = fmaf(kf, diy, iy0);

        const float xf = floorf(ix);
        const float yf = floorf(iy);
        const float wx = ix - xf;
        const float wy = iy - yf;

        int x0 = (int)xf;
        int y0 = (int)yf;
        x0 = max(-PAD, min(x0, Ww));                 // any OOB tap -> zero halo
        y0 = max(-PAD, min(y0, Hh));

        const float2* q = &sh[(y0 + PAD) * PITCH + (x0 + PAD)];
        const float2 v00 = q[0];
        const float2 v01 = q[1];
        const float2 v10 = q[PITCH];
        const float2 v11 = q[PITCH + 1];

        // blend z per tap, then bilinear lerp
        const float t00 = fmaf(v00.x, wz0, v00.y * wz1);
        const float t01 = fmaf(v01.x, wz0, v01.y * wz1);
        const float t10 = fmaf(v10.x, wz0, v10.y * wz1);
        const float t11 = fmaf(v11.x, wz0, v11.y * wz1);

        const float h0 = fmaf(t01 - t00, wx, t00);
        const float h1 = fmaf(t11 - t10, wx, t10);
        outp[k * 8 * Ww] = fmaf(h1 - h0, wy, h0);
    }
}

extern "C" void kernel_launch(void* const* d_in, const int* in_sizes, int n_in,
                              void* d_out, int out_size) {
    const float* feature_map = (const float*)d_in[0];
    const float* para_code   = (const float*)d_in[1];
    const float* W_c = (const float*)d_in[2];
    const float* b_c = (const float*)d_in[3];
    const float* W_s = (const float*)d_in[4];
    const float* b_s = (const float*)d_in[5];
    const float* W_r = (const float*)d_in[6];
    const float* b_r = (const float*)d_in[7];
    const float* W_t = (const float*)d_in[8];
    const float* b_t = (const float*)d_in[9];
    float* out = (float*)d_out;

    params_kernel<<<Bsz, 1024>>>(para_code, W_c, b_c, W_s, b_s, W_r, b_r, W_t, b_t);
    sample_kernel<<<Bsz * Dd, 512>>>(feature_map, out);
}

// round 5
// speedup vs baseline: 2.3046x; 1.0756x over previous
#include <cuda_runtime.h>
#include <math.h>

#define PI_F 3.14159f

// Fixed problem shape: B=4, D=C=256, H=W=64, P=256
#define Bsz 4
#define Dd  256
#define Hh  64
#define Ww  64
#define Pp  256

// Scratch / per-(b,d) transform parameters
__device__ float g_p[Bsz * Pp];
__device__ float g_scale[Bsz * Dd];
__device__ float g_cos[Bsz * Dd];
__device__ float g_sin[Bsz * Dd];
__device__ float g_t0[Bsz * Dd];
__device__ float g_t1[Bsz * Dd];

// ---------------------------------------------------------------------------
// mlp1: p = relu(para @ W_c + b_c).  Grid (8 col-chunks, 4 batches), 256 thr.
// Thread layout: tc = tid&31 (column within chunk), j = tid>>5 (k-split 0..7).
// ---------------------------------------------------------------------------
__global__ void __launch_bounds__(256) mlp1_kernel(
        const float* __restrict__ para,
        const float* __restrict__ W_c, const float* __restrict__ b_c) {
    __shared__ float spara[Pp];
    __shared__ float part[8][32];

    const int chunk = blockIdx.x;       // 0..7
    const int b     = blockIdx.y;       // 0..3
    const int tid   = threadIdx.x;
    const int tc    = tid & 31;
    const int j     = tid >> 5;
    const int t     = chunk * 32 + tc;  // global column

    spara[tid] = para[b * Pp + tid];
    __syncthreads();

    float acc = 0.0f;
    const int k0 = j * 32;
#pragma unroll 8
    for (int kk = 0; kk < 32; ++kk) {
        const int k = k0 + kk;
        acc = fmaf(spara[k], W_c[k * Pp + t], acc);
    }
    part[j][tc] = acc;
    __syncthreads();

    if (tid < 32) {
        float v = b_c[chunk * 32 + tid];
#pragma unroll
        for (int jj = 0; jj < 8; ++jj) v += part[jj][tid];
        g_p[b * Pp + chunk * 32 + tid] = fmaxf(v, 0.0f);
    }
}

// ---------------------------------------------------------------------------
// mlp2: four heads + transcendentals.  Grid (8 col-chunks, 4 batches), 256 thr.
// ---------------------------------------------------------------------------
__global__ void __launch_bounds__(256) mlp2_kernel(
        const float* __restrict__ W_s, const float* __restrict__ b_s,
        const float* __restrict__ W_r, const float* __restrict__ b_r,
        const float* __restrict__ W_t, const float* __restrict__ b_t) {
    __shared__ float sp[Pp];
    __shared__ float part[8][32][4];

    const int chunk = blockIdx.x;
    const int b     = blockIdx.y;
    const int tid   = threadIdx.x;
    const int tc    = tid & 31;
    const int j     = tid >> 5;
    const int t     = chunk * 32 + tc;

    sp[tid] = g_p[b * Pp + tid];
    __syncthreads();

    float as = 0.0f, ar = 0.0f, at0 = 0.0f, at1 = 0.0f;
    const int k0 = j * 32;
    const float2* __restrict__ W_t2 = (const float2*)W_t;
#pragma unroll 4
    for (int kk = 0; kk < 32; ++kk) {
        const int k = k0 + kk;
        const float pk = sp[k];
        as  = fmaf(pk, W_s[k * Pp + t], as);
        ar  = fmaf(pk, W_r[k * Pp + t], ar);
        const float2 wt = W_t2[k * Pp + t];
        at0 = fmaf(pk, wt.x, at0);
        at1 = fmaf(pk, wt.y, at1);
    }
    part[j][tc][0] = as;
    part[j][tc][1] = ar;
    part[j][tc][2] = at0;
    part[j][tc][3] = at1;
    __syncthreads();

    if (tid < 32) {
        const int tg = chunk * 32 + tid;
        float vs  = b_s[tg];
        float vr  = b_r[tg];
        float v0  = b_t[2 * tg];
        float v1  = b_t[2 * tg + 1];
#pragma unroll
        for (int jj = 0; jj < 8; ++jj) {
            vs += part[jj][tid][0];
            vr += part[jj][tid][1];
            v0 += part[jj][tid][2];
            v1 += part[jj][tid][3];
        }
        const float scale = 2.0f / (1.0f + expf(-vs));
        const float angle = tanhf(vr) * PI_F;

        const int idx = b * Dd + tg;
        g_scale[idx] = scale;
        g_cos[idx]   = cosf(angle);
        g_sin[idx]   = sinf(angle);
        g_t0[idx]    = tanhf(v0);
        g_t1[idx]    = tanhf(v1);
    }
}

// ---------------------------------------------------------------------------
// sample kernel: one CTA per (b,d), 256 threads, 6 CTAs/SM.
// Planes interleaved as float2, 2-wide zero halo, odd pitch for banks.
// ---------------------------------------------------------------------------
#define PAD    2
#define NCOLS  (Ww + 2 * PAD)           // 68 used columns
#define PITCH  69                        // odd pitch (bank-friendly)
#define PROWS  (Hh + 2 * PAD)           // 68
#define NHALO  (2 * 2 * PITCH + (Hh) * 5)   // rows 0,1,66,67 full + 5 side cells per interior row

__global__ void __launch_bounds__(256, 6) sample_kernel(const float* __restrict__ vol,
                                                        float* __restrict__ out) {
    __shared__ float2 sh[PROWS * PITCH];   // 68*69*8 = 37536 B

    const int bd  = blockIdx.x;
    const int b   = bd >> 8;
    const int d   = bd & 255;
    const int tid = threadIdx.x;

    const float sc = g_scale[bd];
    const float c  = g_cos[bd];
    const float s  = g_sin[bd];
    const float t0 = g_t0[bd];
    const float t1 = g_t1[bd];

    // z -> iz (reference op order)
    const float gz  = 2.0f * ((float)d / (float)(Dd - 1)) - 1.0f;
    const float iz  = ((gz + 1.0f) * (float)Dd - 1.0f) * 0.5f;
    const float z0f = floorf(iz);
    const float wz1 = iz - z0f;
    const float wz0 = 1.0f - wz1;
    const int   z0  = (int)z0f;

    const float* base = vol + (size_t)b * Dd * Hh * Ww;
    const bool z0ok = (z0 >= 0) && (z0 < Dd);
    const bool z1ok = (z0 + 1 >= 0) && (z0 + 1 < Dd);
    const float4* p0v = (const float4*)(base + (size_t)(z0ok ? z0 : 0) * (Hh * Ww));
    const float4* p1v = (const float4*)(base + (size_t)(z1ok ? z0 + 1 : 0) * (Hh * Ww));
    const float4 zero4 = make_float4(0.f, 0.f, 0.f, 0.f);

    // --- halo zeroing (596 cells) and interior fill in ONE phase ---
    // halo cells: 4 full rows (0,1,66,67) of PITCH, plus interior rows' cols {0,1,66,67,68}
    for (int i = tid; i < NHALO; i += 256) {
        int row, col;
        if (i < 4 * PITCH) {
            const int r = i / PITCH;
            row = (r < 2) ? r : (Hh + r);          // 0,1,66,67
            col = i - r * PITCH;
        } else {
            const int m = i - 4 * PITCH;
            row = 2 + m / 5;
            const int cc = m - (m / 5) * 5;
            col = (cc < 2) ? cc : (Hh + cc);       // 0,1,66,67,68
        }
        sh[row * PITCH + col] = make_float2(0.f, 0.f);
    }

    // interior fill: 1024 groups of 4 x-consecutive pixels -> 4 float2 each
#pragma unroll
    for (int jj = 0; jj < 4; ++jj) {
        const int g  = tid + jj * 256;
        const int y  = g >> 4;
        const int x4 = (g & 15) << 2;
        const float4 a  = z0ok ? p0v[g] : zero4;
        const float4 bb = z1ok ? p1v[g] : zero4;
        float2* dst = &sh[(y + PAD) * PITCH + (x4 + PAD)];
        dst[0] = make_float2(a.x, bb.x);
        dst[1] = make_float2(a.y, bb.y);
        dst[2] = make_float2(a.z, bb.z);
        dst[3] = make_float2(a.w, bb.w);
    }
    __syncthreads();

    // px constant per thread; py = py0 + 4k  ->  ix, iy affine in k
    const int px  = tid & 63;
    const int py0 = tid >> 6;                      // 0..3

    const float gx  = fmaf((float)px,  2.0f / 63.0f, -1.0f);
    const float gy0 = fmaf((float)py0, 2.0f / 63.0f, -1.0f);
    const float dgy = 4.0f * (2.0f / 63.0f);

    const float tx0 = (c * gx - s * gy0) * sc + t0;
    const float ty0 = (s * gx + c * gy0) * sc + t1;
    const float ix0 = fmaf(tx0, 32.0f, 31.5f);     // ((tx+1)*64-1)*0.5
    const float iy0 = fmaf(ty0, 32.0f, 31.5f);
    const float dix = -s * sc * dgy * 32.0f;
    const float diy =  c * sc * dgy * 32.0f;

    float* outp = out + (size_t)bd * (Hh * Ww) + py0 * Ww + px;

#pragma unroll 4
    for (int k = 0; k < 16; ++k) {
        const float kf = (float)k;
        const float ix = fmaf(kf, dix, ix0);
        const float iy = fmaf(kf, diy, iy0);

        const float xf = floorf(ix);
        const float yf = floorf(iy);
        const float wx = ix - xf;
        const float wy = iy - yf;

        int x0 = (int)xf;
        int y0 = (int)yf;
        x0 = max(-PAD, min(x0, Ww));               // OOB taps land in zero halo
        y0 = max(-PAD, min(y0, Hh));

        const float2* q = &sh[(y0 + PAD) * PITCH + (x0 + PAD)];
        const float2 v00 = q[0];
        const float2 v01 = q[1];
        const float2 v10 = q[PITCH];
        const float2 v11 = q[PITCH + 1];

        const float t00 = fmaf(v00.x, wz0, v00.y * wz1);
        const float t01 = fmaf(v01.x, wz0, v01.y * wz1);
        const float t10 = fmaf(v10.x, wz0, v10.y * wz1);
        const float t11 = fmaf(v11.x, wz0, v11.y * wz1);

        const float h0 = fmaf(t01 - t00, wx, t00);
        const float h1 = fmaf(t11 - t10, wx, t10);
        outp[k * 4 * Ww] = fmaf(h1 - h0, wy, h0);
    }
}

extern "C" void kernel_launch(void* const* d_in, const int* in_sizes, int n_in,
                              void* d_out, int out_size) {
    const float* feature_map = (const float*)d_in[0];
    const float* para_code   = (const float*)d_in[1];
    const float* W_c = (const float*)d_in[2];
    const float* b_c = (const float*)d_in[3];
    const float* W_s = (const float*)d_in[4];
    const float* b_s = (const float*)d_in[5];
    const float* W_r = (const float*)d_in[6];
    const float* b_r = (const float*)d_in[7];
    const float* W_t = (const float*)d_in[8];
    const float* b_t = (const float*)d_in[9];
    float* out = (float*)d_out;

    mlp1_kernel<<<dim3(8, 4), 256>>>(para_code, W_c, b_c);
    mlp2_kernel<<<dim3(8, 4), 256>>>(W_s, b_s, W_r, b_r, W_t, b_t);
    sample_kernel<<<Bsz * Dd, 256>>>(feature_map, out);
}